// round 16
// baseline (speedup 1.0000x reference)
#include <cuda_runtime.h>
#include <math.h>
#include <stdint.h>

#define LL 1024
#define NB 8
#define CC 1024
#define HH 16
#define HD 64
#define MM (LL*NB)          // 8192
#define C3 (3*CC)           // 3072
#define NHH (NB*HH)         // 128
#define LOGIT_MAX 4.605170185988091f
#define KIT 64              // K=1024 -> 64 k16 stages

// ---- scratch (device globals) ----
__device__ float g_qkv[(size_t)MM * C3];
__device__ float g_q[(size_t)NHH * LL * 128];  // pair-float4 hi/lo rows
__device__ float g_k[(size_t)NHH * LL * 128];  // pair-float4 hi/lo rows
__device__ float g_v[(size_t)NHH * LL * HD];   // paired-frag tiles
__device__ float g_xp[(size_t)MM * CC];    // packed x
__device__ float g_op[(size_t)MM * CC];    // packed attn-out (written by flash)
__device__ float g_w1p[(size_t)C3 * CC];   // packed in_proj_weight (paired B)
__device__ float g_w2p[(size_t)CC * CC];   // packed out_w (paired B)

__device__ __forceinline__ float tf32r(float x) {
    uint32_t u;
    asm("cvt.rna.tf32.f32 %0, %1;" : "=r"(u) : "f"(x));
    return __uint_as_float(u);
}
__device__ __forceinline__ uint32_t smem_u32(const void* p) {
    uint32_t a;
    asm("{ .reg .u64 t; cvta.to.shared.u64 t, %1; cvt.u32.u64 %0, t; }" : "=r"(a) : "l"(p));
    return a;
}
__device__ __forceinline__ void cp16(uint32_t dst, const void* src) {
    asm volatile("cp.async.cg.shared.global [%0], [%1], 16;" :: "r"(dst), "l"(src));
}
__device__ __forceinline__ void cp_commit() {
    asm volatile("cp.async.commit_group;");
}
__device__ __forceinline__ void cp_wait2() {
    asm volatile("cp.async.wait_group 2;");
}
__device__ __forceinline__ void cp_wait1() {
    asm volatile("cp.async.wait_group 1;");
}
__device__ __forceinline__ void mma_tf32_16x8x8(float* d, const uint32_t* a, const uint32_t* b) {
    asm volatile(
        "mma.sync.aligned.m16n8k8.row.col.f32.tf32.tf32.f32 "
        "{%0,%1,%2,%3}, {%4,%5,%6,%7}, {%8,%9}, {%0,%1,%2,%3};\n"
        : "+f"(d[0]), "+f"(d[1]), "+f"(d[2]), "+f"(d[3])
        : "r"(a[0]), "r"(a[1]), "r"(a[2]), "r"(a[3]), "r"(b[0]), "r"(b[1]));
}

// ============================================================
// Pack helpers (device bodies), fused into ONE launch.
// ============================================================
__device__ __forceinline__ void pack_a_body(const float* __restrict__ src,
                                            float* __restrict__ dst, int blk) {
    const size_t d = (size_t)blk * 256 + threadIdx.x;
    const int fi   = (int)(d & 511);
    const size_t sid = d >> 9;
    const int mb = (int)(sid >> 6);
    const int kb = (int)(sid & 63);
    const int c  = fi >> 8;
    const int mt = (fi >> 5) & 7;
    const int lane = fi & 31;
    const int g  = lane >> 2;
    const int kq = lane & 3;
    const int r0 = mb*128 + mt*16 + g;
    const int k0 = kb*16 + c*8 + kq;
    float4 o;
    o.x = tf32r(src[(size_t)r0      * 1024 + k0]);
    o.y = tf32r(src[(size_t)(r0+8)  * 1024 + k0]);
    o.z = tf32r(src[(size_t)r0      * 1024 + k0 + 4]);
    o.w = tf32r(src[(size_t)(r0+8)  * 1024 + k0 + 4]);
    reinterpret_cast<float4*>(dst)[d] = o;
}

__device__ __forceinline__ void pack_b_body(const float* __restrict__ src,
                                            float* __restrict__ dst, int blk) {
    const size_t d = (size_t)blk * 256 + threadIdx.x;
    const int fi   = (int)(d & 511);
    const size_t sid = d >> 9;
    const int nb = (int)(sid >> 6);
    const int kb = (int)(sid & 63);
    const int c  = fi >> 8;
    const int u  = (fi >> 5) & 7;
    const int lane = fi & 31;
    const int g  = lane >> 2;
    const int kq = lane & 3;
    const int c0 = nb*128 + u*16 + g;
    const int k0 = kb*16 + c*8 + kq;
    float4 o;
    o.x = tf32r(src[(size_t)c0     * 1024 + k0]);
    o.y = tf32r(src[(size_t)c0     * 1024 + k0 + 4]);
    o.z = tf32r(src[(size_t)(c0+8) * 1024 + k0]);
    o.w = tf32r(src[(size_t)(c0+8) * 1024 + k0 + 4]);
    reinterpret_cast<float4*>(dst)[d] = o;
}

__global__ __launch_bounds__(256)
void pack_all(const float* __restrict__ x, const float* __restrict__ w1,
              const float* __restrict__ w2,
              float* __restrict__ xp, float* __restrict__ w1p,
              float* __restrict__ w2p) {
    const int b = blockIdx.x;
    if (b < MM)            pack_a_body(x,  xp,  b);
    else if (b < MM + C3)  pack_b_body(w1, w1p, b - MM);
    else                   pack_b_body(w2, w2p, b - MM - C3);
}

// ============================================================
// tf32 mma.sync GEMM, 4-stage pipeline, paired b-frags.
// For qkv (Ncols==C3), v-CTAs (n0>=2048) scatter tf32(acc+bias)
// directly into g_v paired-frag layout and skip the g_qkv write.
// ============================================================
#define GEMM_SMEM (4*4096*4)

__global__ __launch_bounds__(256, 2)
void gemm_tf32_pk(const float* __restrict__ Ap, const float* __restrict__ Bp,
                  const float* __restrict__ bias, float* __restrict__ C,
                  int Ncols) {
    extern __shared__ float sm[];
    const uint32_t smb = smem_u32(sm);
    const int t  = threadIdx.x;
    const int wid  = t >> 5;
    const int lane = t & 31;
    const int g  = lane >> 2;
    const int kq = lane & 3;
    const int wm4 = (wid >> 2) * 4;
    const int wnp = (wid & 3) * 2;
    const int m0 = blockIdx.y * 128;
    const int n0 = blockIdx.x * 128;

    const float* Ab = Ap + (size_t)blockIdx.y * KIT * 2048;
    const float* Bb = Bp + (size_t)blockIdx.x * KIT * 2048;

    float acc[4][4][4] = {};

    #define ISSUE(j)                                                        \
    {                                                                       \
        const uint32_t sb = smb + ((j) & 3) * 16384;                        \
        const float* ag = Ab + (size_t)(j) * 2048;                          \
        const float* bg = Bb + (size_t)(j) * 2048;                          \
        cp16(sb +            t*16, ag + t*4);                               \
        cp16(sb +  4096    + t*16, ag + 1024 + t*4);                        \
        cp16(sb +  8192    + t*16, bg + t*4);                               \
        cp16(sb + 12288    + t*16, bg + 1024 + t*4);                        \
    }

    ISSUE(0); cp_commit();
    ISSUE(1); cp_commit();
    ISSUE(2); cp_commit();

    for (int i = 0; i < KIT; i++) {
        cp_wait2();
        __syncthreads();
        const float* as = sm + (i & 3) * 4096;
        const float* bs = as + 2048;
        #pragma unroll
        for (int c = 0; c < 2; c++) {
            uint32_t a[4][4], b[4][2];
            #pragma unroll
            for (int ti = 0; ti < 4; ti++) {
                float4 af = *reinterpret_cast<const float4*>(
                    &as[(c*8 + wm4 + ti)*128 + lane*4]);
                a[ti][0] = __float_as_uint(af.x);
                a[ti][1] = __float_as_uint(af.y);
                a[ti][2] = __float_as_uint(af.z);
                a[ti][3] = __float_as_uint(af.w);
            }
            #pragma unroll
            for (int u = 0; u < 2; u++) {
                float4 bf = *reinterpret_cast<const float4*>(
                    &bs[(c*8 + wnp + u)*128 + lane*4]);
                b[u*2+0][0] = __float_as_uint(bf.x);
                b[u*2+0][1] = __float_as_uint(bf.y);
                b[u*2+1][0] = __float_as_uint(bf.z);
                b[u*2+1][1] = __float_as_uint(bf.w);
            }
            #pragma unroll
            for (int ti = 0; ti < 4; ti++)
                #pragma unroll
                for (int j = 0; j < 4; j++)
                    mma_tf32_16x8x8(acc[ti][j], a[ti], b[j]);
        }
        const int jn = i + 3;
        if (jn < KIT) ISSUE(jn);
        cp_commit();
    }
    #undef ISSUE

    const bool vpart = (Ncols == C3) && (n0 >= 2048);
    if (!vpart) {
        #pragma unroll
        for (int ti = 0; ti < 4; ti++) {
            const int r0 = m0 + wm4*16 + ti*16 + g;
            #pragma unroll
            for (int j = 0; j < 4; j++) {
                const int c0 = n0 + (wnp*2 + j)*8 + 2*kq;
                const float bx = bias[c0], by = bias[c0+1];
                float2 lo, hi;
                lo.x = acc[ti][j][0] + bx; lo.y = acc[ti][j][1] + by;
                hi.x = acc[ti][j][2] + bx; hi.y = acc[ti][j][3] + by;
                *reinterpret_cast<float2*>(&C[(size_t)r0 * Ncols + c0]) = lo;
                *reinterpret_cast<float2*>(&C[(size_t)(r0+8) * Ncols + c0]) = hi;
            }
        }
    } else {
        // fused v-scatter: mirror of norm_scatter's v-branch indexing
        #pragma unroll
        for (int ti = 0; ti < 4; ti++) {
            const int mA = m0 + wm4*16 + ti*16 + g;
            #pragma unroll
            for (int j = 0; j < 4; j++) {
                const int cbase = n0 + (wnp*2 + j)*8 + 2*kq;
                #pragma unroll
                for (int e = 0; e < 2; e++) {
                    const int ccol = cbase + e;
                    const float bb = bias[ccol];
                    const int vcol = ccol - 2048;
                    const int h = vcol >> 6, d = vcol & 63;
                    const int u = d >> 4, jo = (d >> 3) & 1, gj = d & 7;
                    const int doff = u*32 + gj*4 + 2*jo;
                    #pragma unroll
                    for (int rh = 0; rh < 2; rh++) {
                        const int m = mA + rh*8;
                        const int l = m >> 3, n = m & 7;
                        const int nh = n*16 + h;
                        const int key = l & 63, tile = l >> 6;
                        const int kb = key >> 3, kqv = key & 3, up = (key >> 2) & 1;
                        const size_t base = ((size_t)nh*16 + tile) * 4096
                                          + (size_t)(kb*4 + kqv) * 128 + up;
                        g_v[base + doff] = tf32r(acc[ti][j][rh*2 + e] + bb);
                    }
                }
            }
        }
    }
}

// ============================================================
// Normalize + scatter, q/k ONLY (v handled by gemm epilogue).
// ============================================================
__global__ __launch_bounds__(256)
void norm_scatter_kernel(const float* __restrict__ logit_scale) {
    const int warp = (blockIdx.x * blockDim.x + threadIdx.x) >> 5;
    const int lane = threadIdx.x & 31;
    const int tsel = warp / (NHH * LL);          // 0=q 1=k (grid covers 2/3)
    const int rr   = warp - tsel * (NHH * LL);
    const int nh   = rr >> 10;
    const int l    = rr & 1023;
    const int n    = nh >> 4;
    const int h    = nh & 15;
    const size_t src = (size_t)(l * NB + n) * C3 + (size_t)tsel * CC + h * HD;
    float v0 = g_qkv[src + lane];
    float v1 = g_qkv[src + lane + 32];
    float s = v0*v0 + v1*v1;
    #pragma unroll
    for (int o = 16; o > 0; o >>= 1) s += __shfl_xor_sync(0xffffffffu, s, o);
    float inv = 1.0f / fmaxf(sqrtf(s), 1e-12f);
    if (tsel == 0) inv *= expf(fminf(logit_scale[h], LOGIT_MAX));
    v0 *= inv; v1 *= inv;
    float hi0 = tf32r(v0), lo0 = tf32r(v0 - hi0);
    float hi1 = tf32r(v1), lo1 = tf32r(v1 - hi1);
    float hi0p = __shfl_xor_sync(0xffffffffu, hi0, 4);
    float lo0p = __shfl_xor_sync(0xffffffffu, lo0, 4);
    float hi1p = __shfl_xor_sync(0xffffffffu, hi1, 4);
    float lo1p = __shfl_xor_sync(0xffffffffu, lo1, 4);
    if ((lane & 4) == 0) {
        const int p0 = (lane >> 3) * 4 + (lane & 3);
        float4* row = reinterpret_cast<float4*>(
            (tsel == 0 ? g_q : g_k) + ((size_t)nh * LL + l) * 128);
        row[p0]      = make_float4(hi0, lo0, hi0p, lo0p);
        row[p0 + 16] = make_float4(hi1, lo1, hi1p, lo1p);
    }
}

// ============================================================
// Flash attention v6 (unchanged from R15, 803us-proven).
// ============================================================
#define KSTR 144
#define VSTR2 136
#define PSTR 72
#define FL_K 0
#define FL_V (64*KSTR)
#define FL_P (64*KSTR + 32*VSTR2)
#define FLASH_SMEM ((64*KSTR + 32*VSTR2 + 64*PSTR) * (int)sizeof(float))

__global__ __launch_bounds__(128, 3)
void flash_attn_mma(const float* __restrict__ head_scale,
                    const float* __restrict__ logit_scale) {
    extern __shared__ float smf[];
    float* Ks = smf + FL_K;
    float* Vs = smf + FL_V;
    float* Ps = smf + FL_P;
    const uint32_t smbK = smem_u32(smf) + FL_K * 4;
    const uint32_t smbV = smem_u32(smf) + FL_V * 4;

    const int t    = threadIdx.x;
    const int w    = t >> 5;
    const int lane = t & 31;
    const int g    = lane >> 2;
    const int kq   = lane & 3;
    const int nh = blockIdx.y;
    const int qt = blockIdx.x;
    const int h  = nh & 15;
    const float* Kg = g_k + (size_t)nh * LL * 128;
    const float* Vg = g_v + (size_t)nh * 16 * 4096;
    const float mfix = expf(fminf(logit_scale[h], LOGIT_MAX));

    const int rA = w*16 + g;
    const int rB = rA + 8;

    #define ISSUE_K(kt)                                                     \
    {                                                                       \
        const float* Kt = Kg + (size_t)(kt) * 64 * 128;                     \
        for (int i = t; i < 2048; i += 128) {                               \
            int r = i >> 5, c = i & 31;                                     \
            cp16(smbK + r*(KSTR*4) + c*16, Kt + r*128 + c*4);               \
        }                                                                   \
    }
    #define ISSUE_V(kt)                                                     \
    {                                                                       \
        const float* Vt = Vg + (size_t)(kt) * 4096;                         \
        for (int i = t; i < 1024; i += 128) {                               \
            int r = i >> 5, c = i & 31;                                     \
            cp16(smbV + r*(VSTR2*4) + c*16, Vt + r*128 + c*4);              \
        }                                                                   \
    }

    ISSUE_K(0); cp_commit();
    ISSUE_V(0); cp_commit();

    uint32_t ah[8][4], al[8][4];
    {
        const float4* Qg4 = reinterpret_cast<const float4*>(
            g_q + ((size_t)nh * LL + qt * 64) * 128);
        #pragma unroll
        for (int kb = 0; kb < 8; kb++) {
            float4 fA = Qg4[rA*32 + kb*4 + kq];
            float4 fB = Qg4[rB*32 + kb*4 + kq];
            ah[kb][0] = __float_as_uint(fA.x);
            ah[kb][1] = __float_as_uint(fB.x);
            ah[kb][2] = __float_as_uint(fA.z);
            ah[kb][3] = __float_as_uint(fB.z);
            al[kb][0] = __float_as_uint(fA.y);
            al[kb][1] = __float_as_uint(fB.y);
            al[kb][2] = __float_as_uint(fA.w);
            al[kb][3] = __float_as_uint(fB.w);
        }
    }

    float acc[8][4] = {};
    float liA = 0.0f, liB = 0.0f;

    for (int kt = 0; kt < 16; kt++) {
        cp_wait1();
        __syncthreads();

        float sd[8][4] = {};
        #pragma unroll
        for (int kb = 0; kb < 8; kb++) {
            #pragma unroll
            for (int j = 0; j < 8; j++) {
                float4 f4 = *reinterpret_cast<const float4*>(
                    &Ks[(j*8 + g)*KSTR + (kb*4 + kq)*4]);
                uint32_t bhi[2] = {__float_as_uint(f4.x), __float_as_uint(f4.z)};
                uint32_t blo[2] = {__float_as_uint(f4.y), __float_as_uint(f4.w)};
                mma_tf32_16x8x8(sd[j], ah[kb], bhi);
                mma_tf32_16x8x8(sd[j], ah[kb], blo);
                mma_tf32_16x8x8(sd[j], al[kb], bhi);
            }
        }

        #pragma unroll
        for (int j = 0; j < 8; j++) {
            float p0 = __expf(sd[j][0] - mfix);
            float p1 = __expf(sd[j][1] - mfix);
            float p2 = __expf(sd[j][2] - mfix);
            float p3 = __expf(sd[j][3] - mfix);
            liA += p0 + p1;
            liB += p2 + p3;
            *reinterpret_cast<float2*>(&Ps[rA*PSTR + j*8 + 2*kq]) =
                make_float2(tf32r(p0), tf32r(p1));
            *reinterpret_cast<float2*>(&Ps[rB*PSTR + j*8 + 2*kq]) =
                make_float2(tf32r(p2), tf32r(p3));
        }

        __syncthreads();
        if (kt + 1 < 16) ISSUE_K(kt + 1);
        cp_commit();

        cp_wait1();
        __syncthreads();

        #pragma unroll
        for (int kb = 0; kb < 8; kb++) {
            uint32_t pa[4];
            pa[0] = __float_as_uint(Ps[rA*PSTR + kb*8+kq]);
            pa[1] = __float_as_uint(Ps[rB*PSTR + kb*8+kq]);
            pa[2] = __float_as_uint(Ps[rA*PSTR + kb*8+kq+4]);
            pa[3] = __float_as_uint(Ps[rB*PSTR + kb*8+kq+4]);
            #pragma unroll
            for (int u = 0; u < 4; u++) {
                float4 fv = *reinterpret_cast<const float4*>(
                    &Vs[(kb*4 + kq)*VSTR2 + u*32 + g*4]);
                uint32_t vb0[2] = {__float_as_uint(fv.x), __float_as_uint(fv.y)};
                uint32_t vb1[2] = {__float_as_uint(fv.z), __float_as_uint(fv.w)};
                mma_tf32_16x8x8(acc[u*2+0], pa, vb0);
                mma_tf32_16x8x8(acc[u*2+1], pa, vb1);
            }
        }

        __syncthreads();
        if (kt + 1 < 16) ISSUE_V(kt + 1);
        cp_commit();
    }
    #undef ISSUE_K
    #undef ISSUE_V

    liA += __shfl_xor_sync(0xffffffffu, liA, 1);
    liA += __shfl_xor_sync(0xffffffffu, liA, 2);
    liB += __shfl_xor_sync(0xffffffffu, liB, 1);
    liB += __shfl_xor_sync(0xffffffffu, liB, 2);

    const int n = nh >> 4;
    const float hs = head_scale[h];
    const float sAf = hs / liA, sBf = hs / liB;
    const bool writer = ((g & 1) == 0) && (kq < 2);
    const size_t mb_base = ((size_t)(qt*4 + w)) * 64;
    float4* op4 = reinterpret_cast<float4*>(g_op);

    #pragma unroll
    for (int j = 0; j < 8; j++) {
        const int kb = h*4 + (j >> 1);
        const int cc = j & 1;
        #pragma unroll
        for (int dk = 0; dk < 2; dk++) {
            const int kq_p = 2*(kq & 1) + dk;
            {
                float v = tf32r(acc[j][dk] * sAf);
                float t2 = __shfl_xor_sync(0xffffffffu, v, 2);
                float t4 = __shfl_xor_sync(0xffffffffu, v, 4);
                float t6 = __shfl_xor_sync(0xffffffffu, v, 6);
                if (writer) {
                    const size_t fi = (mb_base + kb)*512 + cc*256
                                    + (g >> 1)*32 + n*4 + kq_p;
                    op4[fi] = make_float4(v, t4, t2, t6);
                }
            }
            {
                float v = tf32r(acc[j][2+dk] * sBf);
                float t2 = __shfl_xor_sync(0xffffffffu, v, 2);
                float t4 = __shfl_xor_sync(0xffffffffu, v, 4);
                float t6 = __shfl_xor_sync(0xffffffffu, v, 6);
                if (writer) {
                    const size_t fi = (mb_base + kb)*512 + cc*256
                                    + ((g >> 1) + 4)*32 + n*4 + kq_p;
                    op4[fi] = make_float4(v, t4, t2, t6);
                }
            }
        }
    }
}

// ============================================================
extern "C" void kernel_launch(void* const* d_in, const int* in_sizes, int n_in,
                              void* d_out, int out_size) {
    const float* x           = (const float*)d_in[0];
    const float* w_in        = (const float*)d_in[1];
    const float* b_in        = (const float*)d_in[2];
    const float* logit_scale = (const float*)d_in[3];
    const float* head_scale  = (const float*)d_in[4];
    const float* out_w       = (const float*)d_in[5];
    const float* out_b       = (const float*)d_in[6];
    float* out = (float*)d_out;

    float *qkv_p, *xp_p, *op_p, *w1p_p, *w2p_p;
    cudaGetSymbolAddress((void**)&qkv_p, g_qkv);
    cudaGetSymbolAddress((void**)&xp_p,  g_xp);
    cudaGetSymbolAddress((void**)&op_p,  g_op);
    cudaGetSymbolAddress((void**)&w1p_p, g_w1p);
    cudaGetSymbolAddress((void**)&w2p_p, g_w2p);

    cudaFuncSetAttribute(flash_attn_mma,
                         cudaFuncAttributeMaxDynamicSharedMemorySize, FLASH_SMEM);
    cudaFuncSetAttribute(gemm_tf32_pk,
                         cudaFuncAttributeMaxDynamicSharedMemorySize, GEMM_SMEM);

    // fused packs: x | in_proj_weight | out_w in one launch
    pack_all<<<MM + C3 + CC, 256>>>(x, w_in, out_w, xp_p, w1p_p, w2p_p);

    // 1) qkv = x @ W^T + b  (v third scattered directly to g_v)
    gemm_tf32_pk<<<dim3(C3/128, MM/128), 256, GEMM_SMEM>>>(xp_p, w1p_p, b_in, qkv_p, C3);
    // 2) normalize + scatter q/k only
    norm_scatter_kernel<<<(2*NHH*LL)/8, 256>>>(logit_scale);
    // 3) flash attention (writes g_op directly, packed)
    flash_attn_mma<<<dim3(LL/64, NHH), 128, FLASH_SMEM>>>(head_scale, logit_scale);
    // 4) out = o @ out_w^T + out_b
    gemm_tf32_pk<<<dim3(CC/128, MM/128), 256, GEMM_SMEM>>>(op_p, w2p_p, out_b, out, CC);
}

// round 17
// speedup vs baseline: 1.0904x; 1.0904x over previous
#include <cuda_runtime.h>
#include <math.h>
#include <stdint.h>

#define LL 1024
#define NB 8
#define CC 1024
#define HH 16
#define HD 64
#define MM (LL*NB)          // 8192
#define C3 (3*CC)           // 3072
#define NHH (NB*HH)         // 128
#define LOGIT_MAX 4.605170185988091f
#define LOG2E 1.44269504088896f
#define KIT 64              // K=1024 -> 64 k16 stages

// ---- scratch (device globals) ----
__device__ float g_qkv[(size_t)MM * C3];
__device__ float g_q[(size_t)NHH * LL * 128];  // pair-float4 hi/lo rows (q scaled by ls*log2e)
__device__ float g_k[(size_t)NHH * LL * 128];  // pair-float4 hi/lo rows
__device__ float g_v[(size_t)NHH * LL * HD];   // paired-frag tiles
__device__ float g_xp[(size_t)MM * CC];    // packed x
__device__ float g_op[(size_t)MM * CC];    // packed attn-out (written by flash)
__device__ float g_w1p[(size_t)C3 * CC];   // packed in_proj_weight (paired B)
__device__ float g_w2p[(size_t)CC * CC];   // packed out_w (paired B)

__device__ __forceinline__ float tf32r(float x) {
    uint32_t u;
    asm("cvt.rna.tf32.f32 %0, %1;" : "=r"(u) : "f"(x));
    return __uint_as_float(u);
}
__device__ __forceinline__ float ex2f(float x) {
    float r;
    asm("ex2.approx.ftz.f32 %0, %1;" : "=f"(r) : "f"(x));
    return r;
}
__device__ __forceinline__ uint32_t smem_u32(const void* p) {
    uint32_t a;
    asm("{ .reg .u64 t; cvta.to.shared.u64 t, %1; cvt.u32.u64 %0, t; }" : "=r"(a) : "l"(p));
    return a;
}
__device__ __forceinline__ void cp16(uint32_t dst, const void* src) {
    asm volatile("cp.async.cg.shared.global [%0], [%1], 16;" :: "r"(dst), "l"(src));
}
__device__ __forceinline__ void cp_commit() {
    asm volatile("cp.async.commit_group;");
}
__device__ __forceinline__ void cp_wait2() {
    asm volatile("cp.async.wait_group 2;");
}
__device__ __forceinline__ void cp_wait1() {
    asm volatile("cp.async.wait_group 1;");
}
__device__ __forceinline__ void mma_tf32_16x8x8(float* d, const uint32_t* a, const uint32_t* b) {
    asm volatile(
        "mma.sync.aligned.m16n8k8.row.col.f32.tf32.tf32.f32 "
        "{%0,%1,%2,%3}, {%4,%5,%6,%7}, {%8,%9}, {%0,%1,%2,%3};\n"
        : "+f"(d[0]), "+f"(d[1]), "+f"(d[2]), "+f"(d[3])
        : "r"(a[0]), "r"(a[1]), "r"(a[2]), "r"(a[3]), "r"(b[0]), "r"(b[1]));
}

// ============================================================
// Pack helpers (device bodies), fused into ONE launch.
// ============================================================
__device__ __forceinline__ void pack_a_body(const float* __restrict__ src,
                                            float* __restrict__ dst, int blk) {
    const size_t d = (size_t)blk * 256 + threadIdx.x;
    const int fi   = (int)(d & 511);
    const size_t sid = d >> 9;
    const int mb = (int)(sid >> 6);
    const int kb = (int)(sid & 63);
    const int c  = fi >> 8;
    const int mt = (fi >> 5) & 7;
    const int lane = fi & 31;
    const int g  = lane >> 2;
    const int kq = lane & 3;
    const int r0 = mb*128 + mt*16 + g;
    const int k0 = kb*16 + c*8 + kq;
    float4 o;
    o.x = tf32r(src[(size_t)r0      * 1024 + k0]);
    o.y = tf32r(src[(size_t)(r0+8)  * 1024 + k0]);
    o.z = tf32r(src[(size_t)r0      * 1024 + k0 + 4]);
    o.w = tf32r(src[(size_t)(r0+8)  * 1024 + k0 + 4]);
    reinterpret_cast<float4*>(dst)[d] = o;
}

__device__ __forceinline__ void pack_b_body(const float* __restrict__ src,
                                            float* __restrict__ dst, int blk) {
    const size_t d = (size_t)blk * 256 + threadIdx.x;
    const int fi   = (int)(d & 511);
    const size_t sid = d >> 9;
    const int nb = (int)(sid >> 6);
    const int kb = (int)(sid & 63);
    const int c  = fi >> 8;
    const int u  = (fi >> 5) & 7;
    const int lane = fi & 31;
    const int g  = lane >> 2;
    const int kq = lane & 3;
    const int c0 = nb*128 + u*16 + g;
    const int k0 = kb*16 + c*8 + kq;
    float4 o;
    o.x = tf32r(src[(size_t)c0     * 1024 + k0]);
    o.y = tf32r(src[(size_t)c0     * 1024 + k0 + 4]);
    o.z = tf32r(src[(size_t)(c0+8) * 1024 + k0]);
    o.w = tf32r(src[(size_t)(c0+8) * 1024 + k0 + 4]);
    reinterpret_cast<float4*>(dst)[d] = o;
}

__global__ __launch_bounds__(256)
void pack_all(const float* __restrict__ x, const float* __restrict__ w1,
              const float* __restrict__ w2,
              float* __restrict__ xp, float* __restrict__ w1p,
              float* __restrict__ w2p) {
    const int b = blockIdx.x;
    if (b < MM)            pack_a_body(x,  xp,  b);
    else if (b < MM + C3)  pack_b_body(w1, w1p, b - MM);
    else                   pack_b_body(w2, w2p, b - MM - C3);
}

// ============================================================
// tf32 mma.sync GEMM, 4-stage pipeline, paired b-frags.
// For qkv (Ncols==C3), v-CTAs (n0>=2048) scatter tf32(acc+bias)
// directly into g_v paired-frag layout and skip the g_qkv write.
// ============================================================
#define GEMM_SMEM (4*4096*4)

__global__ __launch_bounds__(256, 2)
void gemm_tf32_pk(const float* __restrict__ Ap, const float* __restrict__ Bp,
                  const float* __restrict__ bias, float* __restrict__ C,
                  int Ncols) {
    extern __shared__ float sm[];
    const uint32_t smb = smem_u32(sm);
    const int t  = threadIdx.x;
    const int wid  = t >> 5;
    const int lane = t & 31;
    const int g  = lane >> 2;
    const int kq = lane & 3;
    const int wm4 = (wid >> 2) * 4;
    const int wnp = (wid & 3) * 2;
    const int m0 = blockIdx.y * 128;
    const int n0 = blockIdx.x * 128;

    const float* Ab = Ap + (size_t)blockIdx.y * KIT * 2048;
    const float* Bb = Bp + (size_t)blockIdx.x * KIT * 2048;

    float acc[4][4][4] = {};

    #define ISSUE(j)                                                        \
    {                                                                       \
        const uint32_t sb = smb + ((j) & 3) * 16384;                        \
        const float* ag = Ab + (size_t)(j) * 2048;                          \
        const float* bg = Bb + (size_t)(j) * 2048;                          \
        cp16(sb +            t*16, ag + t*4);                               \
        cp16(sb +  4096    + t*16, ag + 1024 + t*4);                        \
        cp16(sb +  8192    + t*16, bg + t*4);                               \
        cp16(sb + 12288    + t*16, bg + 1024 + t*4);                        \
    }

    ISSUE(0); cp_commit();
    ISSUE(1); cp_commit();
    ISSUE(2); cp_commit();

    for (int i = 0; i < KIT; i++) {
        cp_wait2();
        __syncthreads();
        const float* as = sm + (i & 3) * 4096;
        const float* bs = as + 2048;
        #pragma unroll
        for (int c = 0; c < 2; c++) {
            uint32_t a[4][4], b[4][2];
            #pragma unroll
            for (int ti = 0; ti < 4; ti++) {
                float4 af = *reinterpret_cast<const float4*>(
                    &as[(c*8 + wm4 + ti)*128 + lane*4]);
                a[ti][0] = __float_as_uint(af.x);
                a[ti][1] = __float_as_uint(af.y);
                a[ti][2] = __float_as_uint(af.z);
                a[ti][3] = __float_as_uint(af.w);
            }
            #pragma unroll
            for (int u = 0; u < 2; u++) {
                float4 bf = *reinterpret_cast<const float4*>(
                    &bs[(c*8 + wnp + u)*128 + lane*4]);
                b[u*2+0][0] = __float_as_uint(bf.x);
                b[u*2+0][1] = __float_as_uint(bf.y);
                b[u*2+1][0] = __float_as_uint(bf.z);
                b[u*2+1][1] = __float_as_uint(bf.w);
            }
            #pragma unroll
            for (int ti = 0; ti < 4; ti++)
                #pragma unroll
                for (int j = 0; j < 4; j++)
                    mma_tf32_16x8x8(acc[ti][j], a[ti], b[j]);
        }
        const int jn = i + 3;
        if (jn < KIT) ISSUE(jn);
        cp_commit();
    }
    #undef ISSUE

    const bool vpart = (Ncols == C3) && (n0 >= 2048);
    if (!vpart) {
        #pragma unroll
        for (int ti = 0; ti < 4; ti++) {
            const int r0 = m0 + wm4*16 + ti*16 + g;
            #pragma unroll
            for (int j = 0; j < 4; j++) {
                const int c0 = n0 + (wnp*2 + j)*8 + 2*kq;
                const float bx = bias[c0], by = bias[c0+1];
                float2 lo, hi;
                lo.x = acc[ti][j][0] + bx; lo.y = acc[ti][j][1] + by;
                hi.x = acc[ti][j][2] + bx; hi.y = acc[ti][j][3] + by;
                *reinterpret_cast<float2*>(&C[(size_t)r0 * Ncols + c0]) = lo;
                *reinterpret_cast<float2*>(&C[(size_t)(r0+8) * Ncols + c0]) = hi;
            }
        }
    } else {
        #pragma unroll
        for (int ti = 0; ti < 4; ti++) {
            const int mA = m0 + wm4*16 + ti*16 + g;
            #pragma unroll
            for (int j = 0; j < 4; j++) {
                const int cbase = n0 + (wnp*2 + j)*8 + 2*kq;
                #pragma unroll
                for (int e = 0; e < 2; e++) {
                    const int ccol = cbase + e;
                    const float bb = bias[ccol];
                    const int vcol = ccol - 2048;
                    const int h = vcol >> 6, d = vcol & 63;
                    const int u = d >> 4, jo = (d >> 3) & 1, gj = d & 7;
                    const int doff = u*32 + gj*4 + 2*jo;
                    #pragma unroll
                    for (int rh = 0; rh < 2; rh++) {
                        const int m = mA + rh*8;
                        const int l = m >> 3, n = m & 7;
                        const int nh = n*16 + h;
                        const int key = l & 63, tile = l >> 6;
                        const int kb = key >> 3, kqv = key & 3, up = (key >> 2) & 1;
                        const size_t base = ((size_t)nh*16 + tile) * 4096
                                          + (size_t)(kb*4 + kqv) * 128 + up;
                        g_v[base + doff] = tf32r(acc[ti][j][rh*2 + e] + bb);
                    }
                }
            }
        }
    }
}

// ============================================================
// Normalize + scatter, q/k only. q additionally scaled by LOG2E
// (base-2 softmax downstream; softmax ratios unchanged).
// ============================================================
__global__ __launch_bounds__(256)
void norm_scatter_kernel(const float* __restrict__ logit_scale) {
    const int warp = (blockIdx.x * blockDim.x + threadIdx.x) >> 5;
    const int lane = threadIdx.x & 31;
    const int tsel = warp / (NHH * LL);
    const int rr   = warp - tsel * (NHH * LL);
    const int nh   = rr >> 10;
    const int l    = rr & 1023;
    const int n    = nh >> 4;
    const int h    = nh & 15;
    const size_t src = (size_t)(l * NB + n) * C3 + (size_t)tsel * CC + h * HD;
    float v0 = g_qkv[src + lane];
    float v1 = g_qkv[src + lane + 32];
    float s = v0*v0 + v1*v1;
    #pragma unroll
    for (int o = 16; o > 0; o >>= 1) s += __shfl_xor_sync(0xffffffffu, s, o);
    float inv = 1.0f / fmaxf(sqrtf(s), 1e-12f);
    if (tsel == 0) inv *= expf(fminf(logit_scale[h], LOGIT_MAX)) * LOG2E;
    v0 *= inv; v1 *= inv;
    float hi0 = tf32r(v0), lo0 = tf32r(v0 - hi0);
    float hi1 = tf32r(v1), lo1 = tf32r(v1 - hi1);
    float hi0p = __shfl_xor_sync(0xffffffffu, hi0, 4);
    float lo0p = __shfl_xor_sync(0xffffffffu, lo0, 4);
    float hi1p = __shfl_xor_sync(0xffffffffu, hi1, 4);
    float lo1p = __shfl_xor_sync(0xffffffffu, lo1, 4);
    if ((lane & 4) == 0) {
        const int p0 = (lane >> 3) * 4 + (lane & 3);
        float4* row = reinterpret_cast<float4*>(
            (tsel == 0 ? g_q : g_k) + ((size_t)nh * LL + l) * 128);
        row[p0]      = make_float4(hi0, lo0, hi0p, lo0p);
        row[p0 + 16] = make_float4(hi1, lo1, hi1p, lo1p);
    }
}

// ============================================================
// Flash attention v7: 2xTF32 QK (ahi*bhi + ahi*blo; alo dropped,
// -32 regs, -64 MMAs/kt), base-2 softmax p = ex2(S2 - mfix2),
// paired-frag V, fused o-pack epilogue, 3 CTAs/SM.
// ============================================================
#define KSTR 144
#define VSTR2 136
#define PSTR 72
#define FL_K 0
#define FL_V (64*KSTR)
#define FL_P (64*KSTR + 32*VSTR2)
#define FLASH_SMEM ((64*KSTR + 32*VSTR2 + 64*PSTR) * (int)sizeof(float))

__global__ __launch_bounds__(128, 3)
void flash_attn_mma(const float* __restrict__ head_scale,
                    const float* __restrict__ logit_scale) {
    extern __shared__ float smf[];
    float* Ks = smf + FL_K;
    float* Vs = smf + FL_V;
    float* Ps = smf + FL_P;
    const uint32_t smbK = smem_u32(smf) + FL_K * 4;
    const uint32_t smbV = smem_u32(smf) + FL_V * 4;

    const int t    = threadIdx.x;
    const int w    = t >> 5;
    const int lane = t & 31;
    const int g    = lane >> 2;
    const int kq   = lane & 3;
    const int nh = blockIdx.y;
    const int qt = blockIdx.x;
    const int h  = nh & 15;
    const float* Kg = g_k + (size_t)nh * LL * 128;
    const float* Vg = g_v + (size_t)nh * 16 * 4096;
    // S2 = q.k * ls * log2e <= ls*log2e = mfix2
    const float mfix2 = expf(fminf(logit_scale[h], LOGIT_MAX)) * LOG2E;

    const int rA = w*16 + g;
    const int rB = rA + 8;

    #define ISSUE_K(kt)                                                     \
    {                                                                       \
        const float* Kt = Kg + (size_t)(kt) * 64 * 128;                     \
        for (int i = t; i < 2048; i += 128) {                               \
            int r = i >> 5, c = i & 31;                                     \
            cp16(smbK + r*(KSTR*4) + c*16, Kt + r*128 + c*4);               \
        }                                                                   \
    }
    #define ISSUE_V(kt)                                                     \
    {                                                                       \
        const float* Vt = Vg + (size_t)(kt) * 4096;                         \
        for (int i = t; i < 1024; i += 128) {                               \
            int r = i >> 5, c = i & 31;                                     \
            cp16(smbV + r*(VSTR2*4) + c*16, Vt + r*128 + c*4);              \
        }                                                                   \
    }

    ISSUE_K(0); cp_commit();
    ISSUE_V(0); cp_commit();

    // Q hi fragments only -> registers
    uint32_t ah[8][4];
    {
        const float4* Qg4 = reinterpret_cast<const float4*>(
            g_q + ((size_t)nh * LL + qt * 64) * 128);
        #pragma unroll
        for (int kb = 0; kb < 8; kb++) {
            float4 fA = Qg4[rA*32 + kb*4 + kq];
            float4 fB = Qg4[rB*32 + kb*4 + kq];
            ah[kb][0] = __float_as_uint(fA.x);
            ah[kb][1] = __float_as_uint(fB.x);
            ah[kb][2] = __float_as_uint(fA.z);
            ah[kb][3] = __float_as_uint(fB.z);
        }
    }

    float acc[8][4] = {};
    float liA = 0.0f, liB = 0.0f;

    for (int kt = 0; kt < 16; kt++) {
        cp_wait1();
        __syncthreads();

        // ---- S2 = Q2 @ K^T (2xTF32: ahi*(bhi+blo)) ----
        float sd[8][4] = {};
        #pragma unroll
        for (int kb = 0; kb < 8; kb++) {
            #pragma unroll
            for (int j = 0; j < 8; j++) {
                float4 f4 = *reinterpret_cast<const float4*>(
                    &Ks[(j*8 + g)*KSTR + (kb*4 + kq)*4]);
                uint32_t bhi[2] = {__float_as_uint(f4.x), __float_as_uint(f4.z)};
                uint32_t blo[2] = {__float_as_uint(f4.y), __float_as_uint(f4.w)};
                mma_tf32_16x8x8(sd[j], ah[kb], bhi);
                mma_tf32_16x8x8(sd[j], ah[kb], blo);
            }
        }

        // ---- static-max base-2 softmax: p = ex2(S2 - mfix2) ----
        #pragma unroll
        for (int j = 0; j < 8; j++) {
            float p0 = ex2f(sd[j][0] - mfix2);
            float p1 = ex2f(sd[j][1] - mfix2);
            float p2 = ex2f(sd[j][2] - mfix2);
            float p3 = ex2f(sd[j][3] - mfix2);
            liA += p0 + p1;
            liB += p2 + p3;
            *reinterpret_cast<float2*>(&Ps[rA*PSTR + j*8 + 2*kq]) =
                make_float2(tf32r(p0), tf32r(p1));
            *reinterpret_cast<float2*>(&Ps[rB*PSTR + j*8 + 2*kq]) =
                make_float2(tf32r(p2), tf32r(p3));
        }

        __syncthreads();
        if (kt + 1 < 16) ISSUE_K(kt + 1);
        cp_commit();

        cp_wait1();
        __syncthreads();

        // ---- O += P @ V (single tf32, paired V frags) ----
        #pragma unroll
        for (int kb = 0; kb < 8; kb++) {
            uint32_t pa[4];
            pa[0] = __float_as_uint(Ps[rA*PSTR + kb*8+kq]);
            pa[1] = __float_as_uint(Ps[rB*PSTR + kb*8+kq]);
            pa[2] = __float_as_uint(Ps[rA*PSTR + kb*8+kq+4]);
            pa[3] = __float_as_uint(Ps[rB*PSTR + kb*8+kq+4]);
            #pragma unroll
            for (int u = 0; u < 4; u++) {
                float4 fv = *reinterpret_cast<const float4*>(
                    &Vs[(kb*4 + kq)*VSTR2 + u*32 + g*4]);
                uint32_t vb0[2] = {__float_as_uint(fv.x), __float_as_uint(fv.y)};
                uint32_t vb1[2] = {__float_as_uint(fv.z), __float_as_uint(fv.w)};
                mma_tf32_16x8x8(acc[u*2+0], pa, vb0);
                mma_tf32_16x8x8(acc[u*2+1], pa, vb1);
            }
        }

        __syncthreads();
        if (kt + 1 < 16) ISSUE_V(kt + 1);
        cp_commit();
    }
    #undef ISSUE_K
    #undef ISSUE_V

    liA += __shfl_xor_sync(0xffffffffu, liA, 1);
    liA += __shfl_xor_sync(0xffffffffu, liA, 2);
    liB += __shfl_xor_sync(0xffffffffu, liB, 1);
    liB += __shfl_xor_sync(0xffffffffu, liB, 2);

    // ---- fused o-pack epilogue ----
    const int n = nh >> 4;
    const float hs = head_scale[h];
    const float sAf = hs / liA, sBf = hs / liB;
    const bool writer = ((g & 1) == 0) && (kq < 2);
    const size_t mb_base = ((size_t)(qt*4 + w)) * 64;
    float4* op4 = reinterpret_cast<float4*>(g_op);

    #pragma unroll
    for (int j = 0; j < 8; j++) {
        const int kb = h*4 + (j >> 1);
        const int cc = j & 1;
        #pragma unroll
        for (int dk = 0; dk < 2; dk++) {
            const int kq_p = 2*(kq & 1) + dk;
            {
                float v = tf32r(acc[j][dk] * sAf);
                float t2 = __shfl_xor_sync(0xffffffffu, v, 2);
                float t4 = __shfl_xor_sync(0xffffffffu, v, 4);
                float t6 = __shfl_xor_sync(0xffffffffu, v, 6);
                if (writer) {
                    const size_t fi = (mb_base + kb)*512 + cc*256
                                    + (g >> 1)*32 + n*4 + kq_p;
                    op4[fi] = make_float4(v, t4, t2, t6);
                }
            }
            {
                float v = tf32r(acc[j][2+dk] * sBf);
                float t2 = __shfl_xor_sync(0xffffffffu, v, 2);
                float t4 = __shfl_xor_sync(0xffffffffu, v, 4);
                float t6 = __shfl_xor_sync(0xffffffffu, v, 6);
                if (writer) {
                    const size_t fi = (mb_base + kb)*512 + cc*256
                                    + ((g >> 1) + 4)*32 + n*4 + kq_p;
                    op4[fi] = make_float4(v, t4, t2, t6);
                }
            }
        }
    }
}

// ============================================================
extern "C" void kernel_launch(void* const* d_in, const int* in_sizes, int n_in,
                              void* d_out, int out_size) {
    const float* x           = (const float*)d_in[0];
    const float* w_in        = (const float*)d_in[1];
    const float* b_in        = (const float*)d_in[2];
    const float* logit_scale = (const float*)d_in[3];
    const float* head_scale  = (const float*)d_in[4];
    const float* out_w       = (const float*)d_in[5];
    const float* out_b       = (const float*)d_in[6];
    float* out = (float*)d_out;

    float *qkv_p, *xp_p, *op_p, *w1p_p, *w2p_p;
    cudaGetSymbolAddress((void**)&qkv_p, g_qkv);
    cudaGetSymbolAddress((void**)&xp_p,  g_xp);
    cudaGetSymbolAddress((void**)&op_p,  g_op);
    cudaGetSymbolAddress((void**)&w1p_p, g_w1p);
    cudaGetSymbolAddress((void**)&w2p_p, g_w2p);

    cudaFuncSetAttribute(flash_attn_mma,
                         cudaFuncAttributeMaxDynamicSharedMemorySize, FLASH_SMEM);
    cudaFuncSetAttribute(gemm_tf32_pk,
                         cudaFuncAttributeMaxDynamicSharedMemorySize, GEMM_SMEM);

    pack_all<<<MM + C3 + CC, 256>>>(x, w_in, out_w, xp_p, w1p_p, w2p_p);

    // 1) qkv = x @ W^T + b  (v third scattered directly to g_v)
    gemm_tf32_pk<<<dim3(C3/128, MM/128), 256, GEMM_SMEM>>>(xp_p, w1p_p, b_in, qkv_p, C3);
    // 2) normalize + scatter q/k (q scaled by ls*log2e)
    norm_scatter_kernel<<<(2*NHH*LL)/8, 256>>>(logit_scale);
    // 3) flash attention (2xTF32 QK, base-2 softmax, packed o out)
    flash_attn_mma<<<dim3(LL/64, NHH), 128, FLASH_SMEM>>>(head_scale, logit_scale);
    // 4) out = o @ out_w^T + out_b
    gemm_tf32_pk<<<dim3(CC/128, MM/128), 256, GEMM_SMEM>>>(op_p, w2p_p, out_b, out, CC);
}